// round 2
// baseline (speedup 1.0000x reference)
#include <cuda_runtime.h>
#include <math.h>

// ---------------------------------------------------------------------------
// Problem constants
// ---------------------------------------------------------------------------
#define BATCH 128
#define CIN_MAIN 256     // C + E
#define E_DIM 128
#define NHEAD 8
#define HDIM 16
#define HH 16
#define WW 16
#define HW 256
#define MEM 8
#define DDIM 4096        // HW * E / NH
#define BH (BATCH * NHEAD)   // 1024

// output layout: h_next | c_next | ret_k | ret_v
#define OFF_H  ((size_t)0)
#define OFF_C  ((size_t)4194304)
#define OFF_K  ((size_t)8388608)
#define OFF_V  ((size_t)41943040)

// ---------------------------------------------------------------------------
// Scratch (device globals — allocation-free)
// ---------------------------------------------------------------------------
__device__ float g_cc  [ (size_t)BATCH * 640 * HW ];   // conv_main raw output
__device__ float g_kqv [ (size_t)BATCH * 384 * HW ];   // conv_proj raw output
__device__ float g_q   [ (size_t)BH * DDIM ];          // scaled query
__device__ float g_attn[ (size_t)BH * DDIM ];          // attention output (== (B,E,H,W) layout)
__device__ float g_outp[ (size_t)BATCH * E_DIM * HW ]; // conv_out + residual (pre-LN)
__device__ float g_scores[ BH * MEM ];
__device__ float g_stats [ BATCH * 2 ];                // mu, rsigma per batch

__device__ __forceinline__ float sigmoidf_(float x) { return 1.0f / (1.0f + expf(-x)); }

// ---------------------------------------------------------------------------
// Direct 3x3 SAME conv, fp32.
//   Each CTA: one batch, 32 output channels.
//   Thread: strip of 8 consecutive pixels (half row) x 4 output channels.
//   in_sel:  0 -> use in0/in1 params (in1 = channels >=128), 1 -> g_attn
//   out_sel: 0 -> g_cc, 1 -> g_kqv, 2 -> g_outp
// ---------------------------------------------------------------------------
template<int CIN>
__global__ void __launch_bounds__(256)
conv3x3_kernel(const float* __restrict__ in0, const float* __restrict__ in1,
               const float* __restrict__ wgt, const float* __restrict__ bias,
               const float* __restrict__ res,
               int in_sel, int out_sel, int COUT)
{
    const int b       = blockIdx.y;
    const int oc_base = blockIdx.x * 32;
    const int tid     = threadIdx.x;

    __shared__ float s_in[16][HW];      // 16 in-channels x 256 px
    __shared__ float s_w [16][9][32];   // [cin][tap][oc]

    const float* base_in0 = (in_sel == 1) ? g_attn : in0;

    const int strip = tid & 31;
    const int y     = strip >> 1;
    const int x0    = (strip & 1) * 8;
    const int ocg   = tid >> 5;          // 0..7 -> 4 out channels each

    float acc[8][4];
#pragma unroll
    for (int p = 0; p < 8; p++)
#pragma unroll
        for (int q = 0; q < 4; q++) acc[p][q] = 0.0f;

    const int NCHUNK = CIN / 16;
    for (int ch = 0; ch < NCHUNK; ch++) {
        const int cin_base = ch * 16;
        __syncthreads();
        // load 16 input channels (coalesced)
#pragma unroll
        for (int t = 0; t < 16; t++) {
            const int cg = cin_base + t;
            const float* sp = (cg < 128)
                ? base_in0 + ((size_t)b * 128 + cg) * HW
                : in1      + ((size_t)b * 128 + (cg - 128)) * HW;
            s_in[t][tid] = sp[tid];
        }
        // load weights for 32 oc x 16 cin x 9 taps (coalesced over cin*9)
        for (int idx = tid; idx < 32 * 144; idx += 256) {
            const int oc  = idx / 144;
            const int r   = idx % 144;
            const int ci  = r / 9;
            const int tap = r % 9;
            s_w[ci][tap][oc] =
                wgt[(size_t)(oc_base + oc) * CIN * 9 + (size_t)(cin_base + ci) * 9 + tap];
        }
        __syncthreads();

#pragma unroll 2
        for (int ci = 0; ci < 16; ci++) {
#pragma unroll
            for (int ky = 0; ky < 3; ky++) {
                const int iy = y + ky - 1;
                if (iy < 0 || iy > 15) continue;
                float iv[10];
#pragma unroll
                for (int j = 0; j < 10; j++) {
                    const int ix = x0 + j - 1;
                    iv[j] = (ix >= 0 && ix < 16) ? s_in[ci][iy * 16 + ix] : 0.0f;
                }
#pragma unroll
                for (int kx = 0; kx < 3; kx++) {
#pragma unroll
                    for (int q = 0; q < 4; q++) {
                        const float wv = s_w[ci][ky * 3 + kx][ocg * 4 + q];
#pragma unroll
                        for (int p = 0; p < 8; p++)
                            acc[p][q] = fmaf(iv[p + kx], wv, acc[p][q]);
                    }
                }
            }
        }
    }

    float* outp = (out_sel == 0) ? g_cc : (out_sel == 1) ? g_kqv : g_outp;
#pragma unroll
    for (int q = 0; q < 4; q++) {
        const int oc = oc_base + ocg * 4 + q;
        const float bv = bias[oc];
#pragma unroll
        for (int p = 0; p < 8; p++) {
            const int s = y * 16 + x0 + p;
            float v = acc[p][q] + bv;
            if (res) v += res[((size_t)b * 128 + oc) * HW + s];
            outp[((size_t)b * COUT + oc) * HW + s] = v;
        }
    }
}

// ---------------------------------------------------------------------------
// LSTM gate fusion: c_pre = sigmoid(cc_f)*c_cur + sigmoid(cc_i)*tanh(cc_g)
// ---------------------------------------------------------------------------
__global__ void __launch_bounds__(256)
gates_kernel(const float* __restrict__ c_cur, float* __restrict__ d_out)
{
    const size_t idx = (size_t)blockIdx.x * 256 + threadIdx.x;
    if (idx >= (size_t)BATCH * E_DIM * HW) return;
    const int b = (int)(idx >> 15);
    const int r = (int)(idx & 32767);           // e*256 + s
    const size_t base = (size_t)b * 640 * HW;
    const float ci = g_cc[base + r];
    const float cf = g_cc[base + (size_t)128 * HW + r];
    const float cg = g_cc[base + (size_t)384 * HW + r];
    d_out[OFF_C + idx] = sigmoidf_(cf) * c_cur[idx] + sigmoidf_(ci) * tanhf(cg);
}

// ---------------------------------------------------------------------------
// Scatter kqv: k_new (+pos) -> ret_k slot 7 ; q/64 -> g_q ; v_new -> ret_v slot 7
// ---------------------------------------------------------------------------
__global__ void __launch_bounds__(256)
proj_scatter_kernel(const float* __restrict__ pos_w, float* __restrict__ d_out)
{
    const size_t idx = (size_t)blockIdx.x * 256 + threadIdx.x;
    if (idx >= (size_t)BATCH * 384 * HW) return;
    const int b   = (int)(idx / (384 * HW));
    const int rem = (int)(idx % (384 * HW));
    const int oc  = rem / HW;
    const int s   = rem % HW;
    const int h   = oc / 48;
    const int r   = oc % 48;
    const int grp = r / 16;
    const int c   = r % 16;
    const int d   = c * HW + s;
    const size_t bh = (size_t)b * NHEAD + h;
    const float val = g_kqv[idx];
    if (grp == 0) {
        d_out[OFF_K + (bh * MEM + 7) * DDIM + d] =
            val + pos_w[(size_t)7 * 32768 + (size_t)h * DDIM + d];
    } else if (grp == 1) {
        g_q[bh * DDIM + d] = val * 0.015625f;   // 1/sqrt(4096)
    } else {
        d_out[OFF_V + (bh * MEM + 7) * DDIM + d] = val;
    }
}

// ---------------------------------------------------------------------------
// Scores: one CTA per bh. Streams k slots (shifted + pos), writes ret_k[0..6],
// computes dot(q, k_m) for all m.
// ---------------------------------------------------------------------------
__global__ void __launch_bounds__(256)
attn_scores_kernel(const float* __restrict__ concat_k,
                   const float* __restrict__ pos_w,
                   float* __restrict__ ret_k)
{
    const int bh  = blockIdx.x;
    const int h   = bh & 7;
    const int tid = threadIdx.x;

    float qreg[16];
#pragma unroll
    for (int i = 0; i < 16; i++)
        qreg[i] = g_q[(size_t)bh * DDIM + i * 256 + tid];

    __shared__ float red[8];
    for (int m = 0; m < MEM; m++) {
        const float* ks = (m < 7)
            ? concat_k + ((size_t)bh * MEM + (m + 1)) * DDIM
            : ret_k    + ((size_t)bh * MEM + 7) * DDIM;   // slot 7 already has pos
        const float* pw = pos_w + (size_t)m * 32768 + (size_t)h * DDIM;
        float part = 0.0f;
#pragma unroll
        for (int i = 0; i < 16; i++) {
            const int idx = i * 256 + tid;
            float kv = ks[idx];
            if (m < 7) {
                kv += pw[idx];
                ret_k[((size_t)bh * MEM + m) * DDIM + idx] = kv;
            }
            part = fmaf(qreg[i], kv, part);
        }
#pragma unroll
        for (int off = 16; off > 0; off >>= 1)
            part += __shfl_down_sync(0xffffffffu, part, off);
        if ((tid & 31) == 0) red[tid >> 5] = part;
        __syncthreads();
        if (tid == 0) {
            float t = 0.0f;
#pragma unroll
            for (int w2 = 0; w2 < 8; w2++) t += red[w2];
            g_scores[bh * MEM + m] = t;
        }
        __syncthreads();
    }
}

// ---------------------------------------------------------------------------
// Softmax + attention output + v shift. One CTA per bh.
// mask is read as 32-bit words: the reference produces a bool array which the
// harness transports as a 4-byte dtype (int32 0/1 or float32 0.0/1.0). A
// nonzero-bits test is correct for both encodings.
// ---------------------------------------------------------------------------
__global__ void __launch_bounds__(256)
attn_out_kernel(const float* __restrict__ concat_v,
                const unsigned int* __restrict__ mask,
                const float* __restrict__ pos_b,
                float* __restrict__ ret_v)
{
    const int bh  = blockIdx.x;
    const int h   = bh & 7;
    const int tid = threadIdx.x;
    __shared__ float w8[MEM];

    if (tid == 0) {
        float sc[MEM];
        float mx = -1e30f;
#pragma unroll
        for (int m = 0; m < MEM; m++) {
            float mf = (m == 7) ? 3.0f : (mask[bh * MEM + m] != 0u ? -1e30f : 0.0f);
            sc[m] = mf + g_scores[bh * MEM + m] + pos_b[m * NHEAD + h];
            mx = fmaxf(mx, sc[m]);
        }
        float ssum = 0.0f;
#pragma unroll
        for (int m = 0; m < MEM; m++) { sc[m] = expf(sc[m] - mx); ssum += sc[m]; }
        const float inv = 1.0f / ssum;
#pragma unroll
        for (int m = 0; m < MEM; m++) w8[m] = sc[m] * inv;
    }
    __syncthreads();

    float wl[MEM];
#pragma unroll
    for (int m = 0; m < MEM; m++) wl[m] = w8[m];

#pragma unroll
    for (int i = 0; i < 16; i++) {
        const int idx = i * 256 + tid;
        float acc = 0.0f;
#pragma unroll
        for (int m = 0; m < MEM; m++) {
            float vv;
            if (m < 7) {
                vv = concat_v[((size_t)bh * MEM + (m + 1)) * DDIM + idx];
                ret_v[((size_t)bh * MEM + m) * DDIM + idx] = vv;
            } else {
                vv = ret_v[((size_t)bh * MEM + 7) * DDIM + idx];
            }
            acc = fmaf(wl[m], vv, acc);
        }
        g_attn[(size_t)bh * DDIM + idx] = acc;   // layout == (B,E,H,W) flat
    }
}

// ---------------------------------------------------------------------------
// LayerNorm statistics per batch over (E,H,W) = 32768 elements
// ---------------------------------------------------------------------------
__global__ void __launch_bounds__(256)
ln_stats_kernel()
{
    const int b   = blockIdx.x;
    const int tid = threadIdx.x;
    const float* p = g_outp + (size_t)b * 32768;
    float s = 0.0f, s2 = 0.0f;
    for (int i = tid; i < 32768; i += 256) {
        const float v = p[i];
        s += v; s2 = fmaf(v, v, s2);
    }
#pragma unroll
    for (int off = 16; off > 0; off >>= 1) {
        s  += __shfl_down_sync(0xffffffffu, s, off);
        s2 += __shfl_down_sync(0xffffffffu, s2, off);
    }
    __shared__ float rs_[8], rs2_[8];
    if ((tid & 31) == 0) { rs_[tid >> 5] = s; rs2_[tid >> 5] = s2; }
    __syncthreads();
    if (tid == 0) {
        float ts = 0.0f, ts2 = 0.0f;
#pragma unroll
        for (int w2 = 0; w2 < 8; w2++) { ts += rs_[w2]; ts2 += rs2_[w2]; }
        const float mu  = ts * (1.0f / 32768.0f);
        const float var = ts2 * (1.0f / 32768.0f) - mu * mu;
        g_stats[b * 2]     = mu;
        g_stats[b * 2 + 1] = rsqrtf(var + 1e-5f);
    }
}

// ---------------------------------------------------------------------------
// Final: LayerNorm apply, c_next = c_pre + a*tanh(ln), h_next = o*tanh(c_next)
// ---------------------------------------------------------------------------
__global__ void __launch_bounds__(256)
final_kernel(const float* __restrict__ norm_w, const float* __restrict__ norm_b,
             float* __restrict__ d_out)
{
    const size_t idx = (size_t)blockIdx.x * 256 + threadIdx.x;
    if (idx >= (size_t)BATCH * E_DIM * HW) return;
    const int b = (int)(idx >> 15);
    const int r = (int)(idx & 32767);
    const float mu = g_stats[b * 2];
    const float rs = g_stats[b * 2 + 1];
    const float ln = (g_outp[idx] - mu) * rs * norm_w[r] + norm_b[r];
    const size_t base = (size_t)b * 640 * HW;
    const float o = sigmoidf_(g_cc[base + (size_t)256 * HW + r]);
    const float a = sigmoidf_(g_cc[base + (size_t)512 * HW + r]);
    const float c = d_out[OFF_C + idx] + a * tanhf(ln);
    d_out[OFF_C + idx] = c;
    d_out[OFF_H + idx] = o * tanhf(c);
}

// ---------------------------------------------------------------------------
// Launch
// ---------------------------------------------------------------------------
extern "C" void kernel_launch(void* const* d_in, const int* in_sizes, int n_in,
                              void* d_out_v, int out_size)
{
    const float* input    = (const float*)d_in[0];
    const float* h_cur    = (const float*)d_in[1];
    const float* c_cur    = (const float*)d_in[2];
    const float* concat_k = (const float*)d_in[3];
    const float* concat_v = (const float*)d_in[4];
    const unsigned int* attn_mask = (const unsigned int*)d_in[5];
    const float* main_w   = (const float*)d_in[6];
    const float* main_b   = (const float*)d_in[7];
    const float* proj_w   = (const float*)d_in[8];
    const float* proj_b   = (const float*)d_in[9];
    const float* out_w    = (const float*)d_in[10];
    const float* out_b    = (const float*)d_in[11];
    const float* norm_w   = (const float*)d_in[12];
    const float* norm_b   = (const float*)d_in[13];
    const float* pos_w    = (const float*)d_in[14];
    const float* pos_b    = (const float*)d_in[15];
    float* d_out = (float*)d_out_v;

    // 1) ConvLSTM main conv: (B, 256, 16,16) -> (B, 640, 16,16) into g_cc
    conv3x3_kernel<256><<<dim3(640 / 32, BATCH), 256>>>(
        input, h_cur, main_w, main_b, nullptr, 0, 0, 640);

    // 2) gates -> c_pre into d_out[c region]
    gates_kernel<<<16384, 256>>>(c_cur, d_out);

    // 3) projection conv: (B,128) -> (B,384) into g_kqv
    conv3x3_kernel<128><<<dim3(384 / 32, BATCH), 256>>>(
        input, nullptr, proj_w, proj_b, nullptr, 0, 1, 384);

    // 4) scatter k_new(+pos)/q/v_new
    proj_scatter_kernel<<<(BATCH * 384 * HW) / 256, 256>>>(pos_w, d_out);

    // 5) scores + ret_k shift
    attn_scores_kernel<<<BH, 256>>>(concat_k, pos_w, d_out + OFF_K);

    // 6) softmax + attn output + ret_v shift
    attn_out_kernel<<<BH, 256>>>(concat_v, attn_mask, pos_b, d_out + OFF_V);

    // 7) output conv + residual into g_outp
    conv3x3_kernel<128><<<dim3(128 / 32, BATCH), 256>>>(
        nullptr, nullptr, out_w, out_b, input, 1, 2, 128);

    // 8) LayerNorm stats
    ln_stats_kernel<<<BATCH, 256>>>();

    // 9) final fusion -> h_next, c_next
    final_kernel<<<16384, 256>>>(norm_w, norm_b, d_out);
}

// round 3
// speedup vs baseline: 2.0438x; 2.0438x over previous
#include <cuda_runtime.h>
#include <math.h>

// ---------------------------------------------------------------------------
// Problem constants
// ---------------------------------------------------------------------------
#define BATCH 128
#define E_DIM 128
#define NHEAD 8
#define HW 256
#define MEM 8
#define DDIM 4096
#define BH 1024

// output layout: h_next | c_next | ret_k | ret_v
#define OFF_H  ((size_t)0)
#define OFF_C  ((size_t)4194304)
#define OFF_K  ((size_t)8388608)
#define OFF_V  ((size_t)41943040)

typedef unsigned long long ull;

// ---------------------------------------------------------------------------
// Scratch (device globals — allocation-free)
// ---------------------------------------------------------------------------
__device__ float g_cc  [(size_t)BATCH * 640 * HW];   // conv_main output
__device__ float g_q   [(size_t)BH * DDIM];          // scaled query
__device__ float g_attn[(size_t)BH * DDIM];          // attention output == (B,E,H,W)
__device__ float g_outp[(size_t)BATCH * E_DIM * HW]; // conv_out + residual

__device__ __forceinline__ float sigmoidf_(float x) { return 1.0f / (1.0f + expf(-x)); }

// ---------------------------------------------------------------------------
// Packed f32x2 helpers (Blackwell FFMA2 — PTX-only)
// ---------------------------------------------------------------------------
#define FMA2(d, a, b, c) \
    asm("fma.rn.f32x2 %0, %1, %2, %3;" : "=l"(d) : "l"(a), "l"(b), "l"(c))

__device__ __forceinline__ ull dup2(float v) {
    ull r; unsigned u = __float_as_uint(v);
    asm("mov.b64 %0, {%1, %1};" : "=l"(r) : "r"(u));
    return r;
}
__device__ __forceinline__ void unpack2(ull v, float& lo, float& hi) {
    unsigned a, b;
    asm("mov.b64 {%0, %1}, %2;" : "=r"(a), "=r"(b) : "l"(v));
    lo = __uint_as_float(a); hi = __uint_as_float(b);
}

// ---------------------------------------------------------------------------
// smem layout for conv: s_in [16ci][16y][20] + s_w [16ci][9tap][64oc]
// ---------------------------------------------------------------------------
#define PADW 20
#define SIN_CH 320          // 16*20 floats per channel
#define SW_CI  576          // 9*64 floats per ci
#define SMEM_FLOATS (16*SIN_CH + 16*SW_CI)
#define SMEM_BYTES  (SMEM_FLOATS * 4)      // 57344

// ---------------------------------------------------------------------------
// Epilogue store: 8 consecutive pixels for one output channel, via 2x float4
//   OUTSEL 0 -> g_cc ; 1 -> proj scatter (k+pos / q/64 / v) ; 2 -> g_outp+res
// ---------------------------------------------------------------------------
template<int OUTSEL>
__device__ __forceinline__ void store8(int oc, int sbase, const float* v, int b,
                                       const float* __restrict__ bias,
                                       const float* __restrict__ resid,
                                       const float* __restrict__ pos_w,
                                       float* __restrict__ d_out)
{
    const float bv = __ldg(bias + oc);
    float o[8];
#pragma unroll
    for (int p = 0; p < 8; p++) o[p] = v[p] + bv;

    if (OUTSEL == 0) {
        float* dst = g_cc + ((size_t)b * 640 + oc) * HW + sbase;
        *(float4*)dst       = make_float4(o[0], o[1], o[2], o[3]);
        *(float4*)(dst + 4) = make_float4(o[4], o[5], o[6], o[7]);
    } else if (OUTSEL == 2) {
        const float* rp = resid + ((size_t)b * 128 + oc) * HW + sbase;
        const float4 r0 = *(const float4*)rp;
        const float4 r1 = *(const float4*)(rp + 4);
        float* dst = g_outp + ((size_t)b * 128 + oc) * HW + sbase;
        *(float4*)dst       = make_float4(o[0]+r0.x, o[1]+r0.y, o[2]+r0.z, o[3]+r0.w);
        *(float4*)(dst + 4) = make_float4(o[4]+r1.x, o[5]+r1.y, o[6]+r1.z, o[7]+r1.w);
    } else {
        const int h = oc / 48, r = oc % 48, grp = r / 16, c = r % 16;
        const size_t bh = (size_t)b * NHEAD + h;
        const size_t d0 = (size_t)c * HW + sbase;
        if (grp == 0) {
            const float* pw = pos_w + (size_t)7 * 32768 + (size_t)h * DDIM + d0;
            const float4 p0 = *(const float4*)pw;
            const float4 p1 = *(const float4*)(pw + 4);
            float* dst = d_out + OFF_K + (bh * MEM + 7) * DDIM + d0;
            *(float4*)dst       = make_float4(o[0]+p0.x, o[1]+p0.y, o[2]+p0.z, o[3]+p0.w);
            *(float4*)(dst + 4) = make_float4(o[4]+p1.x, o[5]+p1.y, o[6]+p1.z, o[7]+p1.w);
        } else if (grp == 1) {
            float* dst = g_q + bh * DDIM + d0;
            const float s = 0.015625f;  // 1/sqrt(4096)
            *(float4*)dst       = make_float4(o[0]*s, o[1]*s, o[2]*s, o[3]*s);
            *(float4*)(dst + 4) = make_float4(o[4]*s, o[5]*s, o[6]*s, o[7]*s);
        } else {
            float* dst = d_out + OFF_V + (bh * MEM + 7) * DDIM + d0;
            *(float4*)dst       = make_float4(o[0], o[1], o[2], o[3]);
            *(float4*)(dst + 4) = make_float4(o[4], o[5], o[6], o[7]);
        }
    }
}

// ---------------------------------------------------------------------------
// Direct 3x3 SAME conv, fp32 accum via packed f32x2 FMA.
//   CTA: one batch x 64 output channels. 256 threads.
//   Thread: strip of 8 px (half row) x 8 oc (as 4 f32x2 pairs).
//   INSEL: 0 -> in0 (+in1 for channels>=128 when CIN=256), 1 -> g_attn
// ---------------------------------------------------------------------------
template<int CIN, int INSEL, int OUTSEL>
__global__ void __launch_bounds__(256)
conv3x3(const float* __restrict__ in0, const float* __restrict__ in1,
        const float* __restrict__ wgt, const float* __restrict__ bias,
        const float* __restrict__ resid, const float* __restrict__ pos_w,
        float* __restrict__ d_out)
{
    extern __shared__ float smem[];
    float* s_in = smem;                 // [16][16][PADW]
    float* s_w  = smem + 16 * SIN_CH;   // [16][9][64]

    const int b       = blockIdx.y;
    const int oc_base = blockIdx.x * 64;
    const int tid     = threadIdx.x;
    const int strip   = tid & 31;
    const int y       = strip >> 1;
    const int x0      = (strip & 1) * 8;
    const int ocg     = tid >> 5;       // 0..7, 8 oc each

    const float* src0 = (INSEL == 1) ? g_attn + (size_t)b * 128 * HW
                                     : in0    + (size_t)b * 128 * HW;
    const float* src1 = (CIN == 256) ? in1 + (size_t)b * 128 * HW : src0;

    ull acc[8][4];
#pragma unroll
    for (int p = 0; p < 8; p++)
#pragma unroll
        for (int q = 0; q < 4; q++) acc[p][q] = 0ULL;

    for (int ch = 0; ch < CIN / 16; ch++) {
        const int cb = ch * 16;
        __syncthreads();
        // input channels, padded layout (conflict-light writes)
#pragma unroll
        for (int t = 0; t < 16; t++) {
            const int cg = cb + t;
            float v;
            if (CIN == 256 && cg >= 128) v = src1[(size_t)(cg - 128) * HW + tid];
            else                         v = src0[(size_t)cg * HW + tid];
            s_in[t * SIN_CH + (tid >> 4) * PADW + (tid & 15)] = v;
        }
        // weights: oc innermost in smem (conflict-free stores, pair loads later)
        for (int idx = tid; idx < 64 * 16 * 9; idx += 256) {
            const int oc  = idx & 63;
            const int r   = idx >> 6;
            const int ci  = r / 9;
            const int tap = r % 9;
            s_w[ci * SW_CI + tap * 64 + oc] =
                wgt[(size_t)(oc_base + oc) * (CIN * 9) + (size_t)(cb + ci) * 9 + tap];
        }
        __syncthreads();

#pragma unroll 1
        for (int ci = 0; ci < 16; ci++) {
            const float* chb = s_in + ci * SIN_CH;
#pragma unroll
            for (int ky = 0; ky < 3; ky++) {
                const int iy = y + ky - 1;
                if (iy < 0 || iy > 15) continue;
                const float* rb = chb + iy * PADW + x0;
                const float4 va = *(const float4*)rb;         // px x0..x0+3
                const float4 vb = *(const float4*)(rb + 4);   // px x0+4..x0+7
                const float vl = (x0 == 0) ? 0.0f : rb[-1];
                const float vr = (x0 == 8) ? 0.0f : rb[8];
                ull dup[10];
                dup[0] = dup2(vl);   dup[1] = dup2(va.x); dup[2] = dup2(va.y);
                dup[3] = dup2(va.z); dup[4] = dup2(va.w); dup[5] = dup2(vb.x);
                dup[6] = dup2(vb.y); dup[7] = dup2(vb.z); dup[8] = dup2(vb.w);
                dup[9] = dup2(vr);
                const float* wb = s_w + ci * SW_CI + ky * 192 + ocg * 8;
#pragma unroll
                for (int kx = 0; kx < 3; kx++) {
#pragma unroll
                    for (int q2 = 0; q2 < 4; q2++) {
                        const ull w2 = *(const ull*)(wb + kx * 64 + q2 * 2);
#pragma unroll
                        for (int p = 0; p < 8; p++)
                            FMA2(acc[p][q2], dup[p + kx], w2, acc[p][q2]);
                    }
                }
            }
        }
    }

    // epilogue: vectorized stores
    const int sbase = y * 16 + x0;
#pragma unroll
    for (int q2 = 0; q2 < 4; q2++) {
        float v0[8], v1[8];
#pragma unroll
        for (int p = 0; p < 8; p++) unpack2(acc[p][q2], v0[p], v1[p]);
        const int oc0 = oc_base + ocg * 8 + q2 * 2;
        store8<OUTSEL>(oc0,     sbase, v0, b, bias, resid, pos_w, d_out);
        store8<OUTSEL>(oc0 + 1, sbase, v1, b, bias, resid, pos_w, d_out);
    }
}

// ---------------------------------------------------------------------------
// LSTM gate fusion: c_pre = sigmoid(cc_f)*c_cur + sigmoid(cc_i)*tanh(cc_g)
// ---------------------------------------------------------------------------
__global__ void __launch_bounds__(256)
gates_kernel(const float* __restrict__ c_cur, float* __restrict__ d_out)
{
    const size_t idx = (size_t)blockIdx.x * 256 + threadIdx.x;
    if (idx >= (size_t)BATCH * E_DIM * HW) return;
    const int b = (int)(idx >> 15);
    const int r = (int)(idx & 32767);
    const size_t base = (size_t)b * 640 * HW;
    const float ci = g_cc[base + r];
    const float cf = g_cc[base + (size_t)128 * HW + r];
    const float cg = g_cc[base + (size_t)384 * HW + r];
    d_out[OFF_C + idx] = sigmoidf_(cf) * c_cur[idx] + sigmoidf_(ci) * tanhf(cg);
}

// ---------------------------------------------------------------------------
// Fused attention: scores (+ ret_k shift w/ pos), softmax, output (+ ret_v shift)
// One CTA of 256 threads per bh.
// ---------------------------------------------------------------------------
__global__ void __launch_bounds__(256)
attn_fused(const float* __restrict__ concat_k, const float* __restrict__ concat_v,
           const unsigned int* __restrict__ mask,
           const float* __restrict__ pos_w, const float* __restrict__ pos_b,
           float* __restrict__ ret_k, float* __restrict__ ret_v)
{
    const int bh  = blockIdx.x;
    const int h   = bh & 7;
    const int tid = threadIdx.x;

    float qreg[16];
#pragma unroll
    for (int i = 0; i < 16; i++)
        qreg[i] = g_q[(size_t)bh * DDIM + i * 256 + tid];

    __shared__ float red[8];
    __shared__ float sc_sh[MEM];
    __shared__ float w8[MEM];

    for (int m = 0; m < MEM; m++) {
        const float* ks = (m < 7)
            ? concat_k + ((size_t)bh * MEM + (m + 1)) * DDIM
            : ret_k    + ((size_t)bh * MEM + 7) * DDIM;   // slot 7 already has pos
        const float* pw = pos_w + (size_t)m * 32768 + (size_t)h * DDIM;
        float part = 0.0f;
#pragma unroll
        for (int i = 0; i < 16; i++) {
            const int idx = i * 256 + tid;
            float kv = ks[idx];
            if (m < 7) {
                kv += pw[idx];
                ret_k[((size_t)bh * MEM + m) * DDIM + idx] = kv;
            }
            part = fmaf(qreg[i], kv, part);
        }
#pragma unroll
        for (int off = 16; off > 0; off >>= 1)
            part += __shfl_down_sync(0xffffffffu, part, off);
        if ((tid & 31) == 0) red[tid >> 5] = part;
        __syncthreads();
        if (tid == 0) {
            float t = 0.0f;
#pragma unroll
            for (int w = 0; w < 8; w++) t += red[w];
            sc_sh[m] = t;
        }
        __syncthreads();
    }

    if (tid == 0) {
        float sc[MEM];
        float mx = -1e30f;
#pragma unroll
        for (int m = 0; m < MEM; m++) {
            float mf = (m == 7) ? 3.0f : (mask[bh * MEM + m] != 0u ? -1e30f : 0.0f);
            sc[m] = mf + sc_sh[m] + pos_b[m * NHEAD + h];
            mx = fmaxf(mx, sc[m]);
        }
        float ssum = 0.0f;
#pragma unroll
        for (int m = 0; m < MEM; m++) { sc[m] = expf(sc[m] - mx); ssum += sc[m]; }
        const float inv = 1.0f / ssum;
#pragma unroll
        for (int m = 0; m < MEM; m++) w8[m] = sc[m] * inv;
    }
    __syncthreads();

    float wl[MEM];
#pragma unroll
    for (int m = 0; m < MEM; m++) wl[m] = w8[m];

#pragma unroll
    for (int i = 0; i < 16; i++) {
        const int idx = i * 256 + tid;
        float acc = 0.0f;
#pragma unroll
        for (int m = 0; m < MEM; m++) {
            float vv;
            if (m < 7) {
                vv = concat_v[((size_t)bh * MEM + (m + 1)) * DDIM + idx];
                ret_v[((size_t)bh * MEM + m) * DDIM + idx] = vv;
            } else {
                vv = ret_v[((size_t)bh * MEM + 7) * DDIM + idx];
            }
            acc = fmaf(wl[m], vv, acc);
        }
        g_attn[(size_t)bh * DDIM + idx] = acc;
    }
}

// ---------------------------------------------------------------------------
// Fused LayerNorm (stats + apply) + final LSTM update. One CTA per batch.
// ---------------------------------------------------------------------------
__global__ void __launch_bounds__(512)
ln_final(const float* __restrict__ norm_w, const float* __restrict__ norm_b,
         float* __restrict__ d_out)
{
    const int b   = blockIdx.x;
    const int tid = threadIdx.x;
    const float* p = g_outp + (size_t)b * 32768;

    float s = 0.0f, s2 = 0.0f;
    for (int i = tid; i < 32768; i += 512) {
        const float v = p[i];
        s += v; s2 = fmaf(v, v, s2);
    }
#pragma unroll
    for (int off = 16; off > 0; off >>= 1) {
        s  += __shfl_down_sync(0xffffffffu, s, off);
        s2 += __shfl_down_sync(0xffffffffu, s2, off);
    }
    __shared__ float rs_[16], rs2_[16];
    __shared__ float sh_mu, sh_rs;
    if ((tid & 31) == 0) { rs_[tid >> 5] = s; rs2_[tid >> 5] = s2; }
    __syncthreads();
    if (tid == 0) {
        float ts = 0.0f, ts2 = 0.0f;
#pragma unroll
        for (int w = 0; w < 16; w++) { ts += rs_[w]; ts2 += rs2_[w]; }
        const float mu  = ts * (1.0f / 32768.0f);
        const float var = ts2 * (1.0f / 32768.0f) - mu * mu;
        sh_mu = mu;
        sh_rs = rsqrtf(var + 1e-5f);
    }
    __syncthreads();

    const float mu = sh_mu, rs = sh_rs;
    const size_t cbase = (size_t)b * 640 * HW;
    for (int i = tid; i < 32768; i += 512) {
        const float ln = (p[i] - mu) * rs * norm_w[i] + norm_b[i];
        const float o  = sigmoidf_(g_cc[cbase + (size_t)256 * HW + i]);
        const float a  = sigmoidf_(g_cc[cbase + (size_t)512 * HW + i]);
        const size_t idx = (size_t)b * 32768 + i;
        const float c = d_out[OFF_C + idx] + a * tanhf(ln);
        d_out[OFF_C + idx] = c;
        d_out[OFF_H + idx] = o * tanhf(c);
    }
}

// ---------------------------------------------------------------------------
// Launch
// ---------------------------------------------------------------------------
extern "C" void kernel_launch(void* const* d_in, const int* in_sizes, int n_in,
                              void* d_out_v, int out_size)
{
    const float* input    = (const float*)d_in[0];
    const float* h_cur    = (const float*)d_in[1];
    const float* c_cur    = (const float*)d_in[2];
    const float* concat_k = (const float*)d_in[3];
    const float* concat_v = (const float*)d_in[4];
    const unsigned int* attn_mask = (const unsigned int*)d_in[5];
    const float* main_w   = (const float*)d_in[6];
    const float* main_b   = (const float*)d_in[7];
    const float* proj_w   = (const float*)d_in[8];
    const float* proj_b   = (const float*)d_in[9];
    const float* out_w    = (const float*)d_in[10];
    const float* out_b    = (const float*)d_in[11];
    const float* norm_w   = (const float*)d_in[12];
    const float* norm_b   = (const float*)d_in[13];
    const float* pos_w    = (const float*)d_in[14];
    const float* pos_b    = (const float*)d_in[15];
    float* d_out = (float*)d_out_v;

    cudaFuncSetAttribute(conv3x3<256,0,0>, cudaFuncAttributeMaxDynamicSharedMemorySize, SMEM_BYTES);
    cudaFuncSetAttribute(conv3x3<128,0,1>, cudaFuncAttributeMaxDynamicSharedMemorySize, SMEM_BYTES);
    cudaFuncSetAttribute(conv3x3<128,1,2>, cudaFuncAttributeMaxDynamicSharedMemorySize, SMEM_BYTES);

    // 1) ConvLSTM main conv: (B,256,16,16) -> (B,640,16,16) into g_cc
    conv3x3<256,0,0><<<dim3(10, BATCH), 256, SMEM_BYTES>>>(
        input, h_cur, main_w, main_b, nullptr, nullptr, d_out);

    // 2) gates -> c_pre into d_out[c region]
    gates_kernel<<<16384, 256>>>(c_cur, d_out);

    // 3) projection conv (B,128)->(B,384), fused scatter to ret_k[7]/g_q/ret_v[7]
    conv3x3<128,0,1><<<dim3(6, BATCH), 256, SMEM_BYTES>>>(
        input, nullptr, proj_w, proj_b, nullptr, pos_w, d_out);

    // 4) fused attention (scores + ret_k shift, softmax, output + ret_v shift)
    attn_fused<<<BH, 256>>>(concat_k, concat_v, attn_mask, pos_w, pos_b,
                            d_out + OFF_K, d_out + OFF_V);

    // 5) output conv + residual into g_outp
    conv3x3<128,1,2><<<dim3(2, BATCH), 256, SMEM_BYTES>>>(
        nullptr, nullptr, out_w, out_b, input, nullptr, d_out);

    // 6) fused LayerNorm + final LSTM update
    ln_final<<<BATCH, 512>>>(norm_w, norm_b, d_out);
}

// round 5
// speedup vs baseline: 5.2373x; 2.5625x over previous
#include <cuda_runtime.h>
#include <cuda_bf16.h>
#include <math.h>

// ---------------------------------------------------------------------------
// Problem constants
// ---------------------------------------------------------------------------
#define BATCH 128
#define E_DIM 128
#define NHEAD 8
#define HW 256
#define MEM 8
#define DDIM 4096
#define BH 1024

#define OFF_H  ((size_t)0)
#define OFF_C  ((size_t)4194304)
#define OFF_K  ((size_t)8388608)
#define OFF_V  ((size_t)41943040)

typedef unsigned int u32;

// ---------------------------------------------------------------------------
// Scratch (device globals — allocation-free)
// ---------------------------------------------------------------------------
__device__ float g_cc  [(size_t)BATCH * 640 * HW];
__device__ float g_q   [(size_t)BH * DDIM];
__device__ float g_attn[(size_t)BH * DDIM];
__device__ float g_outp[(size_t)BATCH * E_DIM * HW];

// Pre-swizzled bf16 A tiles (hi/lo). tile = (mtile*9 + tap)*KC + kc,
// each = 64 oc rows x 64 k, K-major, SW128 swizzle -> 8192 bytes.
__device__ __nv_bfloat16 g_wm_hi[360 * 4096], g_wm_lo[360 * 4096];  // main: 10 mtiles
__device__ __nv_bfloat16 g_wp_hi[108 * 4096], g_wp_lo[108 * 4096];  // proj: 6
__device__ __nv_bfloat16 g_wo_hi[ 36 * 4096], g_wo_lo[ 36 * 4096];  // out:  2

__device__ __forceinline__ float sigmoidf_(float x) { return 1.0f / (1.0f + expf(-x)); }

#define SW128(o) ((o) ^ (((o) >> 3) & 0x70))

__device__ __forceinline__ u32 smem_u32(const void* p) {
    u32 a;
    asm("{ .reg .u64 t; cvta.to.shared.u64 t, %1; cvt.u32.u64 %0, t; }" : "=r"(a) : "l"(p));
    return a;
}

__device__ __forceinline__ void ldm_x4(u32* r, u32 addr) {
    asm volatile("ldmatrix.sync.aligned.m8n8.x4.shared.b16 {%0,%1,%2,%3}, [%4];"
        : "=r"(r[0]), "=r"(r[1]), "=r"(r[2]), "=r"(r[3]) : "r"(addr));
}

__device__ __forceinline__ void mma_bf16(float* c, const u32* a, u32 b0, u32 b1) {
    asm volatile("mma.sync.aligned.m16n8k16.row.col.f32.bf16.bf16.f32 "
        "{%0,%1,%2,%3}, {%4,%5,%6,%7}, {%8,%9}, {%0,%1,%2,%3};"
        : "+f"(c[0]), "+f"(c[1]), "+f"(c[2]), "+f"(c[3])
        : "r"(a[0]), "r"(a[1]), "r"(a[2]), "r"(a[3]), "r"(b0), "r"(b1));
}

// ---------------------------------------------------------------------------
// Weight prep: fp32 [oc][CIN][9] -> swizzled bf16 hi/lo 64x64 K-major tiles
// ---------------------------------------------------------------------------
template<int WSEL>
__global__ void __launch_bounds__(256)
prep_w(const float* __restrict__ w, int ntiles, int KC)
{
    const int idx = blockIdx.x * 256 + threadIdx.x;
    if (idx >= ntiles * 2048) return;
    const int tile = idx >> 11, r = idx & 2047, row = r >> 5, kp = r & 31;
    const int kc = tile % KC, t2 = tile / KC, tap = t2 % 9, mtile = t2 / 9;
    const int CIN = KC * 64;
    const int oc  = mtile * 64 + row;
    const int cin = kc * 64 + kp * 2;
    const size_t wb = ((size_t)oc * CIN + cin) * 9 + tap;
    const float f0 = w[wb], f1 = w[wb + 9];
    const __nv_bfloat16 h0 = __float2bfloat16(f0), h1 = __float2bfloat16(f1);
    const __nv_bfloat16 l0 = __float2bfloat16(f0 - __bfloat162float(h0));
    const __nv_bfloat16 l1 = __float2bfloat16(f1 - __bfloat162float(h1));
    const __nv_bfloat162 hh = __halves2bfloat162(h0, h1);
    const __nv_bfloat162 ll = __halves2bfloat162(l0, l1);
    const u32 off = SW128((u32)(row * 128 + kp * 4));
    __nv_bfloat16* hi = (WSEL == 0) ? g_wm_hi : (WSEL == 1) ? g_wp_hi : g_wo_hi;
    __nv_bfloat16* lo = (WSEL == 0) ? g_wm_lo : (WSEL == 1) ? g_wp_lo : g_wo_lo;
    *(u32*)((char*)hi + (size_t)tile * 8192 + off) = *(const u32*)&hh;
    *(u32*)((char*)lo + (size_t)tile * 8192 + off) = *(const u32*)&ll;
}

// ---------------------------------------------------------------------------
// Epilogue store of a float2 (two px) for one output channel
// ---------------------------------------------------------------------------
template<int OUTSEL>
__device__ __forceinline__ void store2(int ocg, int px, float v0, float v1, int b,
                                       const float* __restrict__ resid,
                                       const float* __restrict__ pos_w,
                                       float* __restrict__ d_out)
{
    if (OUTSEL == 0) {
        *(float2*)(g_cc + ((size_t)b * 640 + ocg) * 256 + px) = make_float2(v0, v1);
    } else if (OUTSEL == 2) {
        const float2 r = *(const float2*)(resid + ((size_t)b * 128 + ocg) * 256 + px);
        *(float2*)(g_outp + ((size_t)b * 128 + ocg) * 256 + px) =
            make_float2(v0 + r.x, v1 + r.y);
    } else {
        const int h = ocg / 48, rr = ocg % 48, grp = rr / 16, c = rr % 16;
        const size_t bh = (size_t)b * 8 + h;
        const size_t d0 = (size_t)c * 256 + px;
        if (grp == 0) {
            const float2 pw = *(const float2*)(pos_w + (size_t)7 * 32768 + (size_t)h * 4096 + d0);
            *(float2*)(d_out + OFF_K + (bh * 8 + 7) * 4096 + d0) =
                make_float2(v0 + pw.x, v1 + pw.y);
        } else if (grp == 1) {
            *(float2*)(g_q + bh * 4096 + d0) = make_float2(v0 * 0.015625f, v1 * 0.015625f);
        } else {
            *(float2*)(d_out + OFF_V + (bh * 8 + 7) * 4096 + d0) = make_float2(v0, v1);
        }
    }
}

// ---------------------------------------------------------------------------
// Implicit-GEMM 3x3 conv via mma.sync bf16x3.
// CTA = (batch, 64-oc tile). 8 warps: 4(M) x 2(N). D[64 oc][256 px] fp32.
// SMEM (81920B): A_hi[0,8K) A_lo[8K,16K) B_hi[16K,48K) B_lo[48K,80K)
//   A: [64 oc][64 k] bf16 K-major SW128; B: [256 px][64 k] bf16 K-major SW128
// ---------------------------------------------------------------------------
#define CONV_SMEM 81920

template<int KC, int INSEL, int OUTSEL>
__global__ void __launch_bounds__(256, 2)
conv_mma(const float* __restrict__ src0, const float* __restrict__ src1,
         const __nv_bfloat16* __restrict__ whi, const __nv_bfloat16* __restrict__ wlo,
         const float* __restrict__ bias, const float* __restrict__ resid,
         const float* __restrict__ pos_w, float* __restrict__ d_out)
{
    extern __shared__ char smem[];
    const int b     = blockIdx.y;
    const int mtile = blockIdx.x;
    const int tid   = threadIdx.x;
    const int wid   = tid >> 5;
    const int lane  = tid & 31;
    const u32 sbase = smem_u32(smem);

    // warp tile position
    const int mrow  = (wid & 3) * 16;
    const int nbase = (wid >> 2) * 128;

    // ldmatrix lane geometry
    const int sel = lane >> 3, r8 = lane & 7;
    const int arow = mrow + r8 + ((sel & 1) << 3);          // A: m0/m1 rows, m2/m3 same
    const u32 aoff = (u32)(arow * 128);
    const u32 arb  = (u32)((arow & 7) << 4);
    const u32 akad = (u32)((sel >> 1) << 4);                // +16B for k8-15 matrices
    const int pxr  = nbase + r8 + ((sel >> 1) << 3);        // B: n rows
    const u32 boff = (u32)(pxr * 128);
    const u32 brb  = (u32)((pxr & 7) << 4);
    const u32 bkad = (u32)((sel & 1) << 4);

    const int y = tid >> 4, xx = tid & 15;

    float acc[64];
#pragma unroll
    for (int i = 0; i < 64; i++) acc[i] = 0.0f;

    for (int kc = 0; kc < KC; kc++) {
        // source chunk for B (shared across the 9 taps -> L1-resident)
        const float* cb;
        if (INSEL == 0) {
            cb = (kc < 2) ? src0 + ((size_t)b * 128 + kc * 64) * 256
                          : src1 + ((size_t)b * 128 + (kc - 2) * 64) * 256;
        } else if (INSEL == 1) {
            cb = src0 + ((size_t)b * 128 + kc * 64) * 256;
        } else {
            cb = g_attn + ((size_t)b * 128 + kc * 64) * 256;
        }

        for (int tap = 0; tap < 9; tap++) {
            const int tile = (mtile * 9 + tap) * KC + kc;
            __syncthreads();   // previous compute done

            // ---- A copy: pre-swizzled 8KB hi + 8KB lo ----
            {
                const uint4* sh = (const uint4*)whi + (size_t)tile * 512;
                const uint4* sl = (const uint4*)wlo + (size_t)tile * 512;
                uint4* dh = (uint4*)smem;
                uint4* dl = (uint4*)(smem + 8192);
                dh[tid] = sh[tid];  dh[tid + 256] = sh[tid + 256];
                dl[tid] = sl[tid];  dl[tid + 256] = sl[tid + 256];
            }

            // ---- B build: shifted pixel row (64 channels), hi/lo bf16 ----
            {
                const int ky = tap / 3, kx = tap % 3;
                const int iy = y + ky - 1, ix = xx + kx - 1;
                const bool valid = ((unsigned)iy < 16u) && ((unsigned)ix < 16u);
                const int sp = iy * 16 + ix;
                char* bhi = smem + 16384;
                char* blo = smem + 49152;
                const u32 rowb = (u32)tid * 128;
#pragma unroll
                for (int g = 0; g < 8; g++) {
                    float v[8];
#pragma unroll
                    for (int j = 0; j < 8; j++)
                        v[j] = valid ? __ldg(cb + (size_t)(g * 8 + j) * 256 + sp) : 0.0f;
                    u32 ph[4], pl[4];
#pragma unroll
                    for (int j = 0; j < 4; j++) {
                        const float a = v[2*j], c = v[2*j+1];
                        const __nv_bfloat16 ha = __float2bfloat16(a), hc = __float2bfloat16(c);
                        const __nv_bfloat16 la = __float2bfloat16(a - __bfloat162float(ha));
                        const __nv_bfloat16 lc = __float2bfloat16(c - __bfloat162float(hc));
                        const __nv_bfloat162 hh = __halves2bfloat162(ha, hc);
                        const __nv_bfloat162 ll = __halves2bfloat162(la, lc);
                        ph[j] = *(const u32*)&hh; pl[j] = *(const u32*)&ll;
                    }
                    const u32 off = SW128(rowb + g * 16);
                    *(uint4*)(bhi + off) = make_uint4(ph[0], ph[1], ph[2], ph[3]);
                    *(uint4*)(blo + off) = make_uint4(pl[0], pl[1], pl[2], pl[3]);
                }
            }

            __syncthreads();

            // ---- compute: 4 k16-steps x 16 n8-tiles x 3 passes ----
#pragma unroll
            for (int q = 0; q < 4; q++) {
                u32 ah[4], al[4];
                const u32 ao = ((u32)(q * 32) + akad) ^ arb;
                ldm_x4(ah, sbase + aoff + ao);
                ldm_x4(al, sbase + 8192 + aoff + ao);
                const u32 bo = ((u32)(q * 32) + bkad) ^ brb;
#pragma unroll
                for (int jj = 0; jj < 8; jj++) {
                    u32 bh[4], bl[4];
                    const u32 ba = boff + (u32)(jj * 2048) + bo;
                    ldm_x4(bh, sbase + 16384 + ba);
                    ldm_x4(bl, sbase + 49152 + ba);
                    float* c0 = acc + jj * 8;
                    float* c1 = acc + jj * 8 + 4;
                    mma_bf16(c0, ah, bh[0], bh[1]);  mma_bf16(c1, ah, bh[2], bh[3]);
                    mma_bf16(c0, ah, bl[0], bl[1]);  mma_bf16(c1, ah, bl[2], bl[3]);
                    mma_bf16(c0, al, bh[0], bh[1]);  mma_bf16(c1, al, bh[2], bh[3]);
                }
            }
        }
    }

    // ---- epilogue: direct gmem stores (float2, sector-aligned) ----
    const int g2 = lane >> 2, qp = lane & 3;
    const int ocg0 = mtile * 64 + mrow + g2;
    const int ocg1 = ocg0 + 8;
    const float bv0 = __ldg(bias + ocg0);
    const float bv1 = __ldg(bias + ocg1);
#pragma unroll
    for (int t = 0; t < 16; t++) {
        const int px = nbase + t * 8 + qp * 2;
        const float* c = acc + t * 4;
        store2<OUTSEL>(ocg0, px, c[0] + bv0, c[1] + bv0, b, resid, pos_w, d_out);
        store2<OUTSEL>(ocg1, px, c[2] + bv1, c[3] + bv1, b, resid, pos_w, d_out);
    }
}

// ---------------------------------------------------------------------------
// LSTM gate fusion
// ---------------------------------------------------------------------------
__global__ void __launch_bounds__(256)
gates_kernel(const float* __restrict__ c_cur, float* __restrict__ d_out)
{
    const size_t idx = (size_t)blockIdx.x * 256 + threadIdx.x;
    if (idx >= (size_t)BATCH * E_DIM * HW) return;
    const int b = (int)(idx >> 15);
    const int r = (int)(idx & 32767);
    const size_t base = (size_t)b * 640 * HW;
    const float ci = g_cc[base + r];
    const float cf = g_cc[base + (size_t)128 * HW + r];
    const float cg = g_cc[base + (size_t)384 * HW + r];
    d_out[OFF_C + idx] = sigmoidf_(cf) * c_cur[idx] + sigmoidf_(ci) * tanhf(cg);
}

// ---------------------------------------------------------------------------
// Fused attention (unchanged, passing)
// ---------------------------------------------------------------------------
__global__ void __launch_bounds__(256)
attn_fused(const float* __restrict__ concat_k, const float* __restrict__ concat_v,
           const unsigned int* __restrict__ mask,
           const float* __restrict__ pos_w, const float* __restrict__ pos_b,
           float* __restrict__ ret_k, float* __restrict__ ret_v)
{
    const int bh  = blockIdx.x;
    const int h   = bh & 7;
    const int tid = threadIdx.x;

    float qreg[16];
#pragma unroll
    for (int i = 0; i < 16; i++)
        qreg[i] = g_q[(size_t)bh * DDIM + i * 256 + tid];

    __shared__ float red[8];
    __shared__ float sc_sh[MEM];
    __shared__ float w8[MEM];

    for (int m = 0; m < MEM; m++) {
        const float* ks = (m < 7)
            ? concat_k + ((size_t)bh * MEM + (m + 1)) * DDIM
            : ret_k    + ((size_t)bh * MEM + 7) * DDIM;
        const float* pw = pos_w + (size_t)m * 32768 + (size_t)h * DDIM;
        float part = 0.0f;
#pragma unroll
        for (int i = 0; i < 16; i++) {
            const int idx = i * 256 + tid;
            float kv = ks[idx];
            if (m < 7) {
                kv += pw[idx];
                ret_k[((size_t)bh * MEM + m) * DDIM + idx] = kv;
            }
            part = fmaf(qreg[i], kv, part);
        }
#pragma unroll
        for (int off = 16; off > 0; off >>= 1)
            part += __shfl_down_sync(0xffffffffu, part, off);
        if ((tid & 31) == 0) red[tid >> 5] = part;
        __syncthreads();
        if (tid == 0) {
            float t = 0.0f;
#pragma unroll
            for (int w = 0; w < 8; w++) t += red[w];
            sc_sh[m] = t;
        }
        __syncthreads();
    }

    if (tid == 0) {
        float sc[MEM];
        float mx = -1e30f;
#pragma unroll
        for (int m = 0; m < MEM; m++) {
            float mf = (m == 7) ? 3.0f : (mask[bh * MEM + m] != 0u ? -1e30f : 0.0f);
            sc[m] = mf + sc_sh[m] + pos_b[m * NHEAD + h];
            mx = fmaxf(mx, sc[m]);
        }
        float ssum = 0.0f;
#pragma unroll
        for (int m = 0; m < MEM; m++) { sc[m] = expf(sc[m] - mx); ssum += sc[m]; }
        const float inv = 1.0f / ssum;
#pragma unroll
        for (int m = 0; m < MEM; m++) w8[m] = sc[m] * inv;
    }
    __syncthreads();

    float wl[MEM];
#pragma unroll
    for (int m = 0; m < MEM; m++) wl[m] = w8[m];

#pragma unroll
    for (int i = 0; i < 16; i++) {
        const int idx = i * 256 + tid;
        float acc = 0.0f;
#pragma unroll
        for (int m = 0; m < MEM; m++) {
            float vv;
            if (m < 7) {
                vv = concat_v[((size_t)bh * MEM + (m + 1)) * DDIM + idx];
                ret_v[((size_t)bh * MEM + m) * DDIM + idx] = vv;
            } else {
                vv = ret_v[((size_t)bh * MEM + 7) * DDIM + idx];
            }
            acc = fmaf(wl[m], vv, acc);
        }
        g_attn[(size_t)bh * DDIM + idx] = acc;
    }
}

// ---------------------------------------------------------------------------
// Fused LayerNorm + final LSTM update (unchanged, passing)
// ---------------------------------------------------------------------------
__global__ void __launch_bounds__(512)
ln_final(const float* __restrict__ norm_w, const float* __restrict__ norm_b,
         float* __restrict__ d_out)
{
    const int b   = blockIdx.x;
    const int tid = threadIdx.x;
    const float* p = g_outp + (size_t)b * 32768;

    float s = 0.0f, s2 = 0.0f;
    for (int i = tid; i < 32768; i += 512) {
        const float v = p[i];
        s += v; s2 = fmaf(v, v, s2);
    }
#pragma unroll
    for (int off = 16; off > 0; off >>= 1) {
        s  += __shfl_down_sync(0xffffffffu, s, off);
        s2 += __shfl_down_sync(0xffffffffu, s2, off);
    }
    __shared__ float rs_[16], rs2_[16];
    __shared__ float sh_mu, sh_rs;
    if ((tid & 31) == 0) { rs_[tid >> 5] = s; rs2_[tid >> 5] = s2; }
    __syncthreads();
    if (tid == 0) {
        float ts = 0.0f, ts2 = 0.0f;
#pragma unroll
        for (int w = 0; w < 16; w++) { ts += rs_[w]; ts2 += rs2_[w]; }
        const float mu  = ts * (1.0f / 32768.0f);
        const float var = ts2 * (1.0f / 32768.0f) - mu * mu;
        sh_mu = mu;
        sh_rs = rsqrtf(var + 1e-5f);
    }
    __syncthreads();

    const float mu = sh_mu, rs = sh_rs;
    const size_t cbase = (size_t)b * 640 * HW;
    for (int i = tid; i < 32768; i += 512) {
        const float ln = (p[i] - mu) * rs * norm_w[i] + norm_b[i];
        const float o  = sigmoidf_(g_cc[cbase + (size_t)256 * HW + i]);
        const float a  = sigmoidf_(g_cc[cbase + (size_t)512 * HW + i]);
        const size_t idx = (size_t)b * 32768 + i;
        const float c = d_out[OFF_C + idx] + a * tanhf(ln);
        d_out[OFF_C + idx] = c;
        d_out[OFF_H + idx] = o * tanhf(c);
    }
}

// ---------------------------------------------------------------------------
// Launch
// ---------------------------------------------------------------------------
extern "C" void kernel_launch(void* const* d_in, const int* in_sizes, int n_in,
                              void* d_out_v, int out_size)
{
    const float* input    = (const float*)d_in[0];
    const float* h_cur    = (const float*)d_in[1];
    const float* c_cur    = (const float*)d_in[2];
    const float* concat_k = (const float*)d_in[3];
    const float* concat_v = (const float*)d_in[4];
    const unsigned int* attn_mask = (const unsigned int*)d_in[5];
    const float* main_w   = (const float*)d_in[6];
    const float* main_b   = (const float*)d_in[7];
    const float* proj_w   = (const float*)d_in[8];
    const float* proj_b   = (const float*)d_in[9];
    const float* out_w    = (const float*)d_in[10];
    const float* out_b    = (const float*)d_in[11];
    const float* norm_w   = (const float*)d_in[12];
    const float* norm_b   = (const float*)d_in[13];
    const float* pos_w    = (const float*)d_in[14];
    const float* pos_b    = (const float*)d_in[15];
    float* d_out = (float*)d_out_v;

    cudaFuncSetAttribute(conv_mma<4,0,0>, cudaFuncAttributeMaxDynamicSharedMemorySize, CONV_SMEM);
    cudaFuncSetAttribute(conv_mma<2,1,1>, cudaFuncAttributeMaxDynamicSharedMemorySize, CONV_SMEM);
    cudaFuncSetAttribute(conv_mma<2,2,2>, cudaFuncAttributeMaxDynamicSharedMemorySize, CONV_SMEM);

    __nv_bfloat16 *wm_hi, *wm_lo, *wp_hi, *wp_lo, *wo_hi, *wo_lo;
    cudaGetSymbolAddress((void**)&wm_hi, g_wm_hi);
    cudaGetSymbolAddress((void**)&wm_lo, g_wm_lo);
    cudaGetSymbolAddress((void**)&wp_hi, g_wp_hi);
    cudaGetSymbolAddress((void**)&wp_lo, g_wp_lo);
    cudaGetSymbolAddress((void**)&wo_hi, g_wo_hi);
    cudaGetSymbolAddress((void**)&wo_lo, g_wo_lo);

    // 0) weight prep
    prep_w<0><<<(360 * 2048) / 256, 256>>>(main_w, 360, 4);
    prep_w<1><<<(108 * 2048) / 256, 256>>>(proj_w, 108, 2);
    prep_w<2><<<( 36 * 2048) / 256, 256>>>(out_w,   36, 2);

    // 1) main conv (B,256)->(B,640) via mma.sync
    conv_mma<4,0,0><<<dim3(10, BATCH), 256, CONV_SMEM>>>(
        input, h_cur, wm_hi, wm_lo, main_b, nullptr, nullptr, d_out);

    // 2) gates -> c_pre
    gates_kernel<<<16384, 256>>>(c_cur, d_out);

    // 3) projection conv (B,128)->(B,384), scatter fused in epilogue
    conv_mma<2,1,1><<<dim3(6, BATCH), 256, CONV_SMEM>>>(
        input, nullptr, wp_hi, wp_lo, proj_b, nullptr, pos_w, d_out);

    // 4) fused attention
    attn_fused<<<BH, 256>>>(concat_k, concat_v, attn_mask, pos_w, pos_b,
                            d_out + OFF_K, d_out + OFF_V);

    // 5) output conv + residual
    conv_mma<2,2,2><<<dim3(2, BATCH), 256, CONV_SMEM>>>(
        nullptr, nullptr, wo_hi, wo_lo, out_b, input, nullptr, d_out);

    // 6) LayerNorm + final LSTM update
    ln_final<<<BATCH, 512>>>(norm_w, norm_b, d_out);
}

// round 6
// speedup vs baseline: 6.6137x; 1.2628x over previous
#include <cuda_runtime.h>
#include <cuda_bf16.h>
#include <math.h>

// ---------------------------------------------------------------------------
// Problem constants
// ---------------------------------------------------------------------------
#define BATCH 128
#define E_DIM 128
#define NHEAD 8
#define HW 256
#define MEM 8
#define DDIM 4096
#define BH 1024

#define OFF_H  ((size_t)0)
#define OFF_C  ((size_t)4194304)
#define OFF_K  ((size_t)8388608)
#define OFF_V  ((size_t)41943040)

typedef unsigned int u32;

// ---------------------------------------------------------------------------
// Scratch (device globals — allocation-free)
// ---------------------------------------------------------------------------
__device__ float g_cc  [(size_t)BATCH * 640 * HW];
__device__ float g_q   [(size_t)BH * DDIM];
__device__ float g_attn[(size_t)BH * DDIM];
__device__ float g_outp[(size_t)BATCH * E_DIM * HW];

// Pre-swizzled bf16 A tiles (hi/lo). tile = (mtile*9 + tap)*KC + kc,
// each = 64 oc rows x 64 k, K-major, SW128 swizzle -> 8192 bytes.
__device__ __nv_bfloat16 g_wm_hi[360 * 4096], g_wm_lo[360 * 4096];  // main: 10 mtiles
__device__ __nv_bfloat16 g_wp_hi[108 * 4096], g_wp_lo[108 * 4096];  // proj: 6
__device__ __nv_bfloat16 g_wo_hi[ 36 * 4096], g_wo_lo[ 36 * 4096];  // out:  2

__device__ __forceinline__ float sigmoidf_(float x) { return 1.0f / (1.0f + expf(-x)); }

#define SW128(o) ((o) ^ (((o) >> 3) & 0x70))

__device__ __forceinline__ u32 smem_u32(const void* p) {
    u32 a;
    asm("{ .reg .u64 t; cvta.to.shared.u64 t, %1; cvt.u32.u64 %0, t; }" : "=r"(a) : "l"(p));
    return a;
}

__device__ __forceinline__ void ldm_x4(u32* r, u32 addr) {
    asm volatile("ldmatrix.sync.aligned.m8n8.x4.shared.b16 {%0,%1,%2,%3}, [%4];"
        : "=r"(r[0]), "=r"(r[1]), "=r"(r[2]), "=r"(r[3]) : "r"(addr));
}

__device__ __forceinline__ void mma_bf16(float* c, const u32* a, u32 b0, u32 b1) {
    asm volatile("mma.sync.aligned.m16n8k16.row.col.f32.bf16.bf16.f32 "
        "{%0,%1,%2,%3}, {%4,%5,%6,%7}, {%8,%9}, {%0,%1,%2,%3};"
        : "+f"(c[0]), "+f"(c[1]), "+f"(c[2]), "+f"(c[3])
        : "r"(a[0]), "r"(a[1]), "r"(a[2]), "r"(a[3]), "r"(b0), "r"(b1));
}

// ---------------------------------------------------------------------------
// Weight prep: fp32 [oc][CIN][9] -> swizzled bf16 hi/lo 64x64 K-major tiles
// ---------------------------------------------------------------------------
template<int WSEL>
__global__ void __launch_bounds__(256)
prep_w(const float* __restrict__ w, int ntiles, int KC)
{
    const int idx = blockIdx.x * 256 + threadIdx.x;
    if (idx >= ntiles * 2048) return;
    const int tile = idx >> 11, r = idx & 2047, row = r >> 5, kp = r & 31;
    const int kc = tile % KC, t2 = tile / KC, tap = t2 % 9, mtile = t2 / 9;
    const int CIN = KC * 64;
    const int oc  = mtile * 64 + row;
    const int cin = kc * 64 + kp * 2;
    const size_t wb = ((size_t)oc * CIN + cin) * 9 + tap;
    const float f0 = w[wb], f1 = w[wb + 9];
    const __nv_bfloat16 h0 = __float2bfloat16(f0), h1 = __float2bfloat16(f1);
    const __nv_bfloat16 l0 = __float2bfloat16(f0 - __bfloat162float(h0));
    const __nv_bfloat16 l1 = __float2bfloat16(f1 - __bfloat162float(h1));
    const __nv_bfloat162 hh = __halves2bfloat162(h0, h1);
    const __nv_bfloat162 ll = __halves2bfloat162(l0, l1);
    const u32 off = SW128((u32)(row * 128 + kp * 4));
    __nv_bfloat16* hi = (WSEL == 0) ? g_wm_hi : (WSEL == 1) ? g_wp_hi : g_wo_hi;
    __nv_bfloat16* lo = (WSEL == 0) ? g_wm_lo : (WSEL == 1) ? g_wp_lo : g_wo_lo;
    *(u32*)((char*)hi + (size_t)tile * 8192 + off) = *(const u32*)&hh;
    *(u32*)((char*)lo + (size_t)tile * 8192 + off) = *(const u32*)&ll;
}

// ---------------------------------------------------------------------------
// Epilogue store of a float2 (two px) for one output channel
// ---------------------------------------------------------------------------
template<int OUTSEL>
__device__ __forceinline__ void store2(int ocg, int px, float v0, float v1, int b,
                                       const float* __restrict__ resid,
                                       const float* __restrict__ pos_w,
                                       float* __restrict__ d_out)
{
    if (OUTSEL == 0) {
        *(float2*)(g_cc + ((size_t)b * 640 + ocg) * 256 + px) = make_float2(v0, v1);
    } else if (OUTSEL == 2) {
        const float2 r = *(const float2*)(resid + ((size_t)b * 128 + ocg) * 256 + px);
        *(float2*)(g_outp + ((size_t)b * 128 + ocg) * 256 + px) =
            make_float2(v0 + r.x, v1 + r.y);
    } else {
        const int h = ocg / 48, rr = ocg % 48, grp = rr / 16, c = rr % 16;
        const size_t bh = (size_t)b * 8 + h;
        const size_t d0 = (size_t)c * 256 + px;
        if (grp == 0) {
            const float2 pw = *(const float2*)(pos_w + (size_t)7 * 32768 + (size_t)h * 4096 + d0);
            *(float2*)(d_out + OFF_K + (bh * 8 + 7) * 4096 + d0) =
                make_float2(v0 + pw.x, v1 + pw.y);
        } else if (grp == 1) {
            *(float2*)(g_q + bh * 4096 + d0) = make_float2(v0 * 0.015625f, v1 * 0.015625f);
        } else {
            *(float2*)(d_out + OFF_V + (bh * 8 + 7) * 4096 + d0) = make_float2(v0, v1);
        }
    }
}

// ---------------------------------------------------------------------------
// Implicit-GEMM 3x3 conv via mma.sync bf16x3 with PADDED-B shift trick.
// CTA = (batch, 64-oc tile). 8 warps: 2(M) x 4(N).
//   warp: M=32 (2 m16 tiles), N=64 (8 n8 tiles) -> 64 fp32 acc.
// B is built ONCE per kc as an 18x18 zero-padded image (324 rows x 64 k,
// hi/lo, K-major SW128, 128B rows). A 3x3 tap = per-lane row offset
// toff = (ky-1)*18 + (kx-1) into the padded array (ldmatrix takes per-lane
// row addresses), so no per-tap rebuild and borders are pre-zeroed.
// SMEM: A_hi[0,8K) A_lo[8K,16K) B_hi[16K,16K+41472) B_lo[+41472)
// ---------------------------------------------------------------------------
#define BPAD_ROWS 324
#define BPAD_BYTES (BPAD_ROWS * 128)          // 41472
#define SB_HI 16384
#define SB_LO (16384 + BPAD_BYTES)            // 57856
#define CONV_SMEM (16384 + 2 * BPAD_BYTES)    // 99328

template<int KC, int INSEL, int OUTSEL>
__global__ void __launch_bounds__(256, 2)
conv_mma(const float* __restrict__ src0, const float* __restrict__ src1,
         const __nv_bfloat16* __restrict__ whi, const __nv_bfloat16* __restrict__ wlo,
         const float* __restrict__ bias, const float* __restrict__ resid,
         const float* __restrict__ pos_w, float* __restrict__ d_out)
{
    extern __shared__ char smem[];
    const int b     = blockIdx.y;
    const int mtile = blockIdx.x;
    const int tid   = threadIdx.x;
    const int wid   = tid >> 5;
    const int lane  = tid & 31;
    const u32 sbase = smem_u32(smem);

    // warp tile position: 2(M) x 4(N)
    const int mrow  = (wid & 1) * 32;      // 2 m16 tiles at mrow, mrow+16
    const int nbase = (wid >> 1) * 64;     // 64 px per warp

    // ldmatrix lane geometry (same fragment relations as the passing R5 kernel)
    const int sel = lane >> 3, r8 = lane & 7;
    // A: matrices 0/1 = rows 0-7/8-15 (k0-7); 2/3 same rows (k8-15)
    const int ar0  = mrow + r8 + ((sel & 1) << 3);
    const int ar1  = ar0 + 16;
    const u32 akad = (u32)((sel >> 1) << 4);
    const u32 ao0b = (u32)(ar0 * 128);
    const u32 ao1b = (u32)(ar1 * 128);
    const u32 asz0 = (u32)((ar0 & 7) << 4);
    const u32 asz1 = (u32)((ar1 & 7) << 4);
    // B: matrices 0/1 = n0-7 (k0-7/k8-15); 2/3 = n8-15
    const int pxr  = nbase + r8 + ((sel >> 1) << 3);   // jj adds 16 px (= +1 y row)
    const u32 bkad = (u32)((sel & 1) << 4);
    const int pad00 = ((pxr >> 4) + 1) * 18 + ((pxr & 15) + 1);

    const int yy = tid >> 4, xx = tid & 15;
    const int padw = (yy + 1) * 18 + (xx + 1);   // interior row this thread fills

    float acc0[32], acc1[32];
#pragma unroll
    for (int i = 0; i < 32; i++) { acc0[i] = 0.0f; acc1[i] = 0.0f; }

    // ---- zero the padded-B border rows once (they persist across kc) ----
    for (int idx = tid; idx < BPAD_ROWS * 8; idx += 256) {
        const int row = idx >> 3, g = idx & 7;
        const int py = row / 18, px = row % 18;
        if (py == 0 || py == 17 || px == 0 || px == 17) {
            const u32 o = (u32)(row * 128 + g * 16);
            *(uint4*)(smem + SB_HI + o) = make_uint4(0, 0, 0, 0);
            *(uint4*)(smem + SB_LO + o) = make_uint4(0, 0, 0, 0);
        }
    }

    for (int kc = 0; kc < KC; kc++) {
        const float* cb;
        if (INSEL == 0) {
            cb = (kc < 2) ? src0 + ((size_t)b * 128 + kc * 64) * 256
                          : src1 + ((size_t)b * 128 + (kc - 2) * 64) * 256;
        } else if (INSEL == 1) {
            cb = src0 + ((size_t)b * 128 + kc * 64) * 256;
        } else {
            cb = g_attn + ((size_t)b * 128 + kc * 64) * 256;
        }

        __syncthreads();   // previous kc compute done -> B writable

        // ---- build padded B interior (once per kc): 256 rows, 64 ch hi/lo ----
        {
            const u32 rowb = (u32)(padw * 128);
            const u32 rswz = (u32)((padw & 7) << 4);
#pragma unroll
            for (int g = 0; g < 8; g++) {
                float v[8];
#pragma unroll
                for (int j = 0; j < 8; j++)
                    v[j] = __ldg(cb + (size_t)(g * 8 + j) * 256 + tid);
                u32 ph[4], pl[4];
#pragma unroll
                for (int j = 0; j < 4; j++) {
                    const float a = v[2*j], c = v[2*j+1];
                    const __nv_bfloat16 ha = __float2bfloat16(a), hc = __float2bfloat16(c);
                    const __nv_bfloat16 la = __float2bfloat16(a - __bfloat162float(ha));
                    const __nv_bfloat16 lc = __float2bfloat16(c - __bfloat162float(hc));
                    const __nv_bfloat162 hh = __halves2bfloat162(ha, hc);
                    const __nv_bfloat162 ll = __halves2bfloat162(la, lc);
                    ph[j] = *(const u32*)&hh; pl[j] = *(const u32*)&ll;
                }
                const u32 o = rowb + ((u32)(g * 16) ^ rswz);
                *(uint4*)(smem + SB_HI + o) = make_uint4(ph[0], ph[1], ph[2], ph[3]);
                *(uint4*)(smem + SB_LO + o) = make_uint4(pl[0], pl[1], pl[2], pl[3]);
            }
        }

        for (int tap = 0; tap < 9; tap++) {
            if (tap > 0) __syncthreads();   // prev tap compute done -> A writable

            // ---- A copy: pre-swizzled 8KB hi + 8KB lo ----
            {
                const int tile = (mtile * 9 + tap) * KC + kc;
                const uint4* sh = (const uint4*)whi + (size_t)tile * 512;
                const uint4* sl = (const uint4*)wlo + (size_t)tile * 512;
                uint4* dh = (uint4*)smem;
                uint4* dl = (uint4*)(smem + 8192);
                dh[tid] = sh[tid];  dh[tid + 256] = sh[tid + 256];
                dl[tid] = sl[tid];  dl[tid + 256] = sl[tid + 256];
            }
            __syncthreads();   // A (and B on first tap) ready

            // ---- compute: shifted reads of padded B ----
            const int toff = (tap / 3 - 1) * 18 + (tap % 3 - 1);
#pragma unroll
            for (int q = 0; q < 4; q++) {
                const u32 ka = (u32)(q * 32) + akad;
                u32 a0h[4], a0l[4], a1h[4], a1l[4];
                const u32 ao0 = ao0b + (ka ^ asz0);
                const u32 ao1 = ao1b + (ka ^ asz1);
                ldm_x4(a0h, sbase + ao0);
                ldm_x4(a0l, sbase + 8192 + ao0);
                ldm_x4(a1h, sbase + ao1);
                ldm_x4(a1l, sbase + 8192 + ao1);
                const u32 kb = (u32)(q * 32) + bkad;
#pragma unroll
                for (int jj = 0; jj < 4; jj++) {
                    const int pr = pad00 + jj * 18 + toff;
                    const u32 bo = (u32)(pr * 128) + (kb ^ ((u32)(pr & 7) << 4));
                    u32 bh[4], bl[4];
                    ldm_x4(bh, sbase + SB_HI + bo);
                    ldm_x4(bl, sbase + SB_LO + bo);
                    float* c0 = acc0 + jj * 8;
                    mma_bf16(c0,     a0h, bh[0], bh[1]);  mma_bf16(c0 + 4, a0h, bh[2], bh[3]);
                    mma_bf16(c0,     a0h, bl[0], bl[1]);  mma_bf16(c0 + 4, a0h, bl[2], bl[3]);
                    mma_bf16(c0,     a0l, bh[0], bh[1]);  mma_bf16(c0 + 4, a0l, bh[2], bh[3]);
                    float* c1 = acc1 + jj * 8;
                    mma_bf16(c1,     a1h, bh[0], bh[1]);  mma_bf16(c1 + 4, a1h, bh[2], bh[3]);
                    mma_bf16(c1,     a1h, bl[0], bl[1]);  mma_bf16(c1 + 4, a1h, bl[2], bl[3]);
                    mma_bf16(c1,     a1l, bh[0], bh[1]);  mma_bf16(c1 + 4, a1l, bh[2], bh[3]);
                }
            }
        }
    }

    // ---- epilogue: direct gmem stores (float2, sector-aligned) ----
    const int g2 = lane >> 2, qp = lane & 3;
#pragma unroll
    for (int mt = 0; mt < 2; mt++) {
        const float* am = mt ? acc1 : acc0;
        const int ocg0 = mtile * 64 + mrow + mt * 16 + g2;
        const int ocg1 = ocg0 + 8;
        const float bv0 = __ldg(bias + ocg0);
        const float bv1 = __ldg(bias + ocg1);
#pragma unroll
        for (int t = 0; t < 8; t++) {
            const int px = nbase + t * 8 + qp * 2;
            const float* c = am + t * 4;
            store2<OUTSEL>(ocg0, px, c[0] + bv0, c[1] + bv0, b, resid, pos_w, d_out);
            store2<OUTSEL>(ocg1, px, c[2] + bv1, c[3] + bv1, b, resid, pos_w, d_out);
        }
    }
}

// ---------------------------------------------------------------------------
// LSTM gate fusion
// ---------------------------------------------------------------------------
__global__ void __launch_bounds__(256)
gates_kernel(const float* __restrict__ c_cur, float* __restrict__ d_out)
{
    const size_t idx = (size_t)blockIdx.x * 256 + threadIdx.x;
    if (idx >= (size_t)BATCH * E_DIM * HW) return;
    const int b = (int)(idx >> 15);
    const int r = (int)(idx & 32767);
    const size_t base = (size_t)b * 640 * HW;
    const float ci = g_cc[base + r];
    const float cf = g_cc[base + (size_t)128 * HW + r];
    const float cg = g_cc[base + (size_t)384 * HW + r];
    d_out[OFF_C + idx] = sigmoidf_(cf) * c_cur[idx] + sigmoidf_(ci) * tanhf(cg);
}

// ---------------------------------------------------------------------------
// Fused attention (unchanged, passing)
// ---------------------------------------------------------------------------
__global__ void __launch_bounds__(256)
attn_fused(const float* __restrict__ concat_k, const float* __restrict__ concat_v,
           const unsigned int* __restrict__ mask,
           const float* __restrict__ pos_w, const float* __restrict__ pos_b,
           float* __restrict__ ret_k, float* __restrict__ ret_v)
{
    const int bh  = blockIdx.x;
    const int h   = bh & 7;
    const int tid = threadIdx.x;

    float qreg[16];
#pragma unroll
    for (int i = 0; i < 16; i++)
        qreg[i] = g_q[(size_t)bh * DDIM + i * 256 + tid];

    __shared__ float red[8];
    __shared__ float sc_sh[MEM];
    __shared__ float w8[MEM];

    for (int m = 0; m < MEM; m++) {
        const float* ks = (m < 7)
            ? concat_k + ((size_t)bh * MEM + (m + 1)) * DDIM
            : ret_k    + ((size_t)bh * MEM + 7) * DDIM;
        const float* pw = pos_w + (size_t)m * 32768 + (size_t)h * DDIM;
        float part = 0.0f;
#pragma unroll
        for (int i = 0; i < 16; i++) {
            const int idx = i * 256 + tid;
            float kv = ks[idx];
            if (m < 7) {
                kv += pw[idx];
                ret_k[((size_t)bh * MEM + m) * DDIM + idx] = kv;
            }
            part = fmaf(qreg[i], kv, part);
        }
#pragma unroll
        for (int off = 16; off > 0; off >>= 1)
            part += __shfl_down_sync(0xffffffffu, part, off);
        if ((tid & 31) == 0) red[tid >> 5] = part;
        __syncthreads();
        if (tid == 0) {
            float t = 0.0f;
#pragma unroll
            for (int w = 0; w < 8; w++) t += red[w];
            sc_sh[m] = t;
        }
        __syncthreads();
    }

    if (tid == 0) {
        float sc[MEM];
        float mx = -1e30f;
#pragma unroll
        for (int m = 0; m < MEM; m++) {
            float mf = (m == 7) ? 3.0f : (mask[bh * MEM + m] != 0u ? -1e30f : 0.0f);
            sc[m] = mf + sc_sh[m] + pos_b[m * NHEAD + h];
            mx = fmaxf(mx, sc[m]);
        }
        float ssum = 0.0f;
#pragma unroll
        for (int m = 0; m < MEM; m++) { sc[m] = expf(sc[m] - mx); ssum += sc[m]; }
        const float inv = 1.0f / ssum;
#pragma unroll
        for (int m = 0; m < MEM; m++) w8[m] = sc[m] * inv;
    }
    __syncthreads();

    float wl[MEM];
#pragma unroll
    for (int m = 0; m < MEM; m++) wl[m] = w8[m];

#pragma unroll
    for (int i = 0; i < 16; i++) {
        const int idx = i * 256 + tid;
        float acc = 0.0f;
#pragma unroll
        for (int m = 0; m < MEM; m++) {
            float vv;
            if (m < 7) {
                vv = concat_v[((size_t)bh * MEM + (m + 1)) * DDIM + idx];
                ret_v[((size_t)bh * MEM + m) * DDIM + idx] = vv;
            } else {
                vv = ret_v[((size_t)bh * MEM + 7) * DDIM + idx];
            }
            acc = fmaf(wl[m], vv, acc);
        }
        g_attn[(size_t)bh * DDIM + idx] = acc;
    }
}

// ---------------------------------------------------------------------------
// Fused LayerNorm + final LSTM update (unchanged, passing)
// ---------------------------------------------------------------------------
__global__ void __launch_bounds__(512)
ln_final(const float* __restrict__ norm_w, const float* __restrict__ norm_b,
         float* __restrict__ d_out)
{
    const int b   = blockIdx.x;
    const int tid = threadIdx.x;
    const float* p = g_outp + (size_t)b * 32768;

    float s = 0.0f, s2 = 0.0f;
    for (int i = tid; i < 32768; i += 512) {
        const float v = p[i];
        s += v; s2 = fmaf(v, v, s2);
    }
#pragma unroll
    for (int off = 16; off > 0; off >>= 1) {
        s  += __shfl_down_sync(0xffffffffu, s, off);
        s2 += __shfl_down_sync(0xffffffffu, s2, off);
    }
    __shared__ float rs_[16], rs2_[16];
    __shared__ float sh_mu, sh_rs;
    if ((tid & 31) == 0) { rs_[tid >> 5] = s; rs2_[tid >> 5] = s2; }
    __syncthreads();
    if (tid == 0) {
        float ts = 0.0f, ts2 = 0.0f;
#pragma unroll
        for (int w = 0; w < 16; w++) { ts += rs_[w]; ts2 += rs2_[w]; }
        const float mu  = ts * (1.0f / 32768.0f);
        const float var = ts2 * (1.0f / 32768.0f) - mu * mu;
        sh_mu = mu;
        sh_rs = rsqrtf(var + 1e-5f);
    }
    __syncthreads();

    const float mu = sh_mu, rs = sh_rs;
    const size_t cbase = (size_t)b * 640 * HW;
    for (int i = tid; i < 32768; i += 512) {
        const float ln = (p[i] - mu) * rs * norm_w[i] + norm_b[i];
        const float o  = sigmoidf_(g_cc[cbase + (size_t)256 * HW + i]);
        const float a  = sigmoidf_(g_cc[cbase + (size_t)512 * HW + i]);
        const size_t idx = (size_t)b * 32768 + i;
        const float c = d_out[OFF_C + idx] + a * tanhf(ln);
        d_out[OFF_C + idx] = c;
        d_out[OFF_H + idx] = o * tanhf(c);
    }
}

// ---------------------------------------------------------------------------
// Launch
// ---------------------------------------------------------------------------
extern "C" void kernel_launch(void* const* d_in, const int* in_sizes, int n_in,
                              void* d_out_v, int out_size)
{
    const float* input    = (const float*)d_in[0];
    const float* h_cur    = (const float*)d_in[1];
    const float* c_cur    = (const float*)d_in[2];
    const float* concat_k = (const float*)d_in[3];
    const float* concat_v = (const float*)d_in[4];
    const unsigned int* attn_mask = (const unsigned int*)d_in[5];
    const float* main_w   = (const float*)d_in[6];
    const float* main_b   = (const float*)d_in[7];
    const float* proj_w   = (const float*)d_in[8];
    const float* proj_b   = (const float*)d_in[9];
    const float* out_w    = (const float*)d_in[10];
    const float* out_b    = (const float*)d_in[11];
    const float* norm_w   = (const float*)d_in[12];
    const float* norm_b   = (const float*)d_in[13];
    const float* pos_w    = (const float*)d_in[14];
    const float* pos_b    = (const float*)d_in[15];
    float* d_out = (float*)d_out_v;

    cudaFuncSetAttribute(conv_mma<4,0,0>, cudaFuncAttributeMaxDynamicSharedMemorySize, CONV_SMEM);
    cudaFuncSetAttribute(conv_mma<2,1,1>, cudaFuncAttributeMaxDynamicSharedMemorySize, CONV_SMEM);
    cudaFuncSetAttribute(conv_mma<2,2,2>, cudaFuncAttributeMaxDynamicSharedMemorySize, CONV_SMEM);

    __nv_bfloat16 *wm_hi, *wm_lo, *wp_hi, *wp_lo, *wo_hi, *wo_lo;
    cudaGetSymbolAddress((void**)&wm_hi, g_wm_hi);
    cudaGetSymbolAddress((void**)&wm_lo, g_wm_lo);
    cudaGetSymbolAddress((void**)&wp_hi, g_wp_hi);
    cudaGetSymbolAddress((void**)&wp_lo, g_wp_lo);
    cudaGetSymbolAddress((void**)&wo_hi, g_wo_hi);
    cudaGetSymbolAddress((void**)&wo_lo, g_wo_lo);

    // 0) weight prep
    prep_w<0><<<(360 * 2048) / 256, 256>>>(main_w, 360, 4);
    prep_w<1><<<(108 * 2048) / 256, 256>>>(proj_w, 108, 2);
    prep_w<2><<<( 36 * 2048) / 256, 256>>>(out_w,   36, 2);

    // 1) main conv (B,256)->(B,640) via mma.sync + padded-B
    conv_mma<4,0,0><<<dim3(10, BATCH), 256, CONV_SMEM>>>(
        input, h_cur, wm_hi, wm_lo, main_b, nullptr, nullptr, d_out);

    // 2) gates -> c_pre
    gates_kernel<<<16384, 256>>>(c_cur, d_out);

    // 3) projection conv (B,128)->(B,384), scatter fused in epilogue
    conv_mma<2,1,1><<<dim3(6, BATCH), 256, CONV_SMEM>>>(
        input, nullptr, wp_hi, wp_lo, proj_b, nullptr, pos_w, d_out);

    // 4) fused attention
    attn_fused<<<BH, 256>>>(concat_k, concat_v, attn_mask, pos_w, pos_b,
                            d_out + OFF_K, d_out + OFF_V);

    // 5) output conv + residual
    conv_mma<2,2,2><<<dim3(2, BATCH), 256, CONV_SMEM>>>(
        nullptr, nullptr, wo_hi, wo_lo, out_b, input, nullptr, d_out);

    // 6) LayerNorm + final LSTM update
    ln_final<<<BATCH, 512>>>(norm_w, norm_b, d_out);
}